// round 15
// baseline (speedup 1.0000x reference)
#include <cuda_runtime.h>
#include <cuda_bf16.h>
#include <cstdint>
#include <cstddef>

// ---------------------------------------------------------------------------
// EventTokenizer persistent kernel — 2 CTAs/SM, 512 threads each, each CTA
// running its OWN 3-stage x 32KB cp.async.bulk pipeline (tests whether the
// ~14 B/cyc/SM stream plateau is per-CTA pipeline serialization or a per-SM
// delivery cap). Static chunk partition; 8 crew blocks do scalars ->
// entropy -> epilogue (hidden under the stream). gsync -> GEMM -> re-zero.
// ---------------------------------------------------------------------------

#define TFRAMES   262144
#define KSEG      64
#define DIN       512
#define DMODEL    256
#define TYPEEMB   32
#define ZDIM      552
#define EPSF      1e-6f
#define CONF_TH   0.3f

#define CH_FRAMES 16
#define CH_BYTES  (CH_FRAMES * DIN * 4)    // 32768
#define NCHUNK    (TFRAMES / CH_FRAMES)    // 16384
#define NSTAGE    3
#define SMEM_DYN  (NSTAGE * CH_BYTES)      // 98304
#define CREW      8
#define NTH       512

// Output layout (float32, reference return order)
#define OUT_TOKENS 0
#define OUT_MASK   16384
#define OUT_TYPE   16448
#define OUT_CONF   16512
#define OUT_SK     16576

__device__ float    g_esum[KSEG * DIN];
__device__ float    g_sumE[KSEG];
__device__ int      g_maxE[KSEG];
__device__ float    g_sumFC[KSEG];
__device__ float    g_sumSC[KSEG * 3];
__device__ float    g_ent[KSEG];
__device__ unsigned g_barc = 0, g_barg = 0;    // grid barrier
__device__ unsigned g_cbc = 0, g_cbg = 0;      // crew barrier

__device__ __forceinline__ void barx(unsigned* cnt, unsigned* gen, unsigned n) {
    __syncthreads();
    if (threadIdx.x == 0) {
        __threadfence();
        unsigned g0 = *(volatile unsigned*)gen;
        if (atomicAdd(cnt, 1u) == n - 1u) {
            *cnt = 0;
            __threadfence();
            atomicAdd(gen, 1u);
        } else {
            while (*(volatile unsigned*)gen == g0) __nanosleep(128);
        }
        __threadfence();
    }
    __syncthreads();
}

__device__ __forceinline__ unsigned s2u(const void* p) {
    return (unsigned)__cvta_generic_to_shared(p);
}
__device__ __forceinline__ void mbar_init(unsigned a, unsigned cnt) {
    asm volatile("mbarrier.init.shared.b64 [%0], %1;" :: "r"(a), "r"(cnt) : "memory");
}
__device__ __forceinline__ void mbar_expect_tx(unsigned a, unsigned bytes) {
    asm volatile("mbarrier.arrive.expect_tx.shared.b64 _, [%0], %1;"
                 :: "r"(a), "r"(bytes) : "memory");
}
__device__ __forceinline__ void bulk_g2s(unsigned dst, const void* src,
                                         unsigned bytes, unsigned mbar) {
    asm volatile("cp.async.bulk.shared::cta.global.mbarrier::complete_tx::bytes "
                 "[%0], [%1], %2, [%3];"
                 :: "r"(dst), "l"(src), "r"(bytes), "r"(mbar) : "memory");
}
__device__ __forceinline__ void mbar_wait(unsigned a, unsigned parity) {
    unsigned done;
    do {
        asm volatile("{\n\t.reg .pred p;\n\t"
                     "mbarrier.try_wait.parity.shared.b64 p, [%1], %2;\n\t"
                     "selp.b32 %0, 1, 0, p;\n\t}"
                     : "=r"(done) : "r"(a), "r"(parity) : "memory");
    } while (!done);
}

__device__ __forceinline__ int seg_of(const int* send, int f) {
    int lo = 0, hi = KSEG - 1;
    #pragma unroll
    for (int it = 0; it < 6; ++it) {
        int mid = (lo + hi) >> 1;
        if (send[mid] > f) hi = mid; else lo = mid + 1;
    }
    return lo;
}

__global__ void __launch_bounds__(NTH)
k_all(const float4* __restrict__ feat,
      const float*  __restrict__ energy,
      const float*  __restrict__ fconf,
      const float*  __restrict__ sconf,
      const int*    __restrict__ segstart,
      const int*    __restrict__ segend,
      const int*    __restrict__ etype,
      const float*  __restrict__ emb,
      const float*  __restrict__ W,
      const float*  __restrict__ bias,
      const int*    __restrict__ fpsp,
      float*        __restrict__ out) {
    extern __shared__ __align__(16) char dsm[];
    __shared__ int   send[KSEG];
    __shared__ float sinv[KSEG];
    __shared__ float z[ZDIM];
    __shared__ alignas(8) unsigned long long mbar[NSTAGE];

    const int tid = threadIdx.x;
    const unsigned G = gridDim.x;
    const int GF = (int)G - CREW;
    if (tid < KSEG) send[tid] = segend[tid];
    if (tid == 0) {
        #pragma unroll
        for (int s = 0; s < NSTAGE; ++s) mbar_init(s2u(&mbar[s]), 1u);
    }
    __syncthreads();

    #define FLUSH4(curv, colv, a) do { \
        float* d_ = &g_esum[(curv) * DIN + (colv) * 4]; \
        atomicAdd(d_ + 0, (a).x); atomicAdd(d_ + 1, (a).y); \
        atomicAdd(d_ + 2, (a).z); atomicAdd(d_ + 3, (a).w); \
        (a).x = (a).y = (a).z = (a).w = 0.f; } while (0)

    // TMA stream over contiguous chunks [c0,c1). 16 warps drain each stage:
    // thread handles frames [h*4, h*4+4), h = tid>>7 in 0..3, col = tid&127.
    auto tma_stream = [&](int c0, int c1) {
        const int n = c1 - c0;
        if (n <= 0) return;
        if (tid == 0) {
            const int pre = n < NSTAGE ? n : NSTAGE;
            for (int l = 0; l < pre; ++l) {
                mbar_expect_tx(s2u(&mbar[l]), CH_BYTES);
                bulk_g2s(s2u(dsm + l * CH_BYTES),
                         (const char*)feat + (size_t)(c0 + l) * CH_BYTES,
                         CH_BYTES, s2u(&mbar[l]));
            }
        }
        const int h   = tid >> 7;        // 0..3, frames [h*4, h*4+4)
        const int col = tid & 127;
        float4 acc = make_float4(0.f, 0.f, 0.f, 0.f);
        int cur = seg_of(send, c0 * CH_FRAMES + h * 4);
        int st = 0, ph = 0;
        for (int l = 0; l < n; ++l) {
            mbar_wait(s2u(&mbar[st]), (unsigned)ph);
            const int f0 = (c0 + l) * CH_FRAMES;
            const float4* sb = (const float4*)(dsm + st * CH_BYTES);
            const int first = f0 + h * 4;
            if (send[cur] <= first) { FLUSH4(cur, col, acc); cur = seg_of(send, first); }
            if (send[cur] >= first + 4) {
                float4 v[4];
                #pragma unroll
                for (int u = 0; u < 4; ++u) v[u] = sb[(h * 4 + u) * 128 + col];
                #pragma unroll
                for (int u = 0; u < 4; ++u) {
                    acc.x += v[u].x; acc.y += v[u].y;
                    acc.z += v[u].z; acc.w += v[u].w;
                }
            } else {
                for (int f = first; f < first + 4; ++f) {
                    if (f >= send[cur]) { FLUSH4(cur, col, acc); cur = seg_of(send, f); }
                    float4 v = sb[(f - f0) * 128 + col];
                    acc.x += v.x; acc.y += v.y; acc.z += v.z; acc.w += v.w;
                }
            }
            __syncthreads();                    // stage fully drained
            if (tid == 0 && l + NSTAGE < n) {
                mbar_expect_tx(s2u(&mbar[st]), CH_BYTES);
                bulk_g2s(s2u(dsm + st * CH_BYTES),
                         (const char*)feat + (size_t)(c0 + l + NSTAGE) * CH_BYTES,
                         CH_BYTES, s2u(&mbar[st]));
            }
            if (++st == NSTAGE) { st = 0; ph ^= 1; }
        }
        FLUSH4(cur, col, acc);
    };

    if ((int)blockIdx.x < GF) {
        const int b  = blockIdx.x;
        const int c0 = (int)(((long long)b * NCHUNK) / GF);
        const int c1 = (int)(((long long)(b + 1) * NCHUNK) / GF);
        tma_stream(c0, c1);
    } else {
        // ============ crew: scalars -> entropy -> epilogue (tail hides under
        // the stream) ============
        const int cb   = blockIdx.x - GF;
        const int g    = cb * NTH + tid;          // 0..4095
        const int lane = g & 31;
        const int w0   = (g >> 5) * 2048;         // warp-contiguous 2048 frames

        {
            int cur = seg_of(send, w0 + lane);
            float sE = 0.f, mx = 0.f, aF = 0.f, s0 = 0.f, s1 = 0.f, s2 = 0.f;
            #define SFLUSH() do { \
                atomicAdd(&g_sumE[cur], sE); \
                atomicMax(&g_maxE[cur], __float_as_int(mx)); \
                atomicAdd(&g_sumFC[cur], aF); \
                atomicAdd(&g_sumSC[cur * 3 + 0], s0); \
                atomicAdd(&g_sumSC[cur * 3 + 1], s1); \
                atomicAdd(&g_sumSC[cur * 3 + 2], s2); \
                sE = mx = aF = s0 = s1 = s2 = 0.f; } while (0)
            #pragma unroll 8
            for (int i = 0; i < 64; ++i) {
                int f = w0 + i * 32 + lane;
                if (f >= send[cur]) { SFLUSH(); while (send[cur] <= f) cur++; }
                float e = energy[f];
                sE += e; mx = fmaxf(mx, e);
                aF += fconf[f];
                s0 += sconf[3 * f + 0]; s1 += sconf[3 * f + 1]; s2 += sconf[3 * f + 2];
            }
            SFLUSH();
            #undef SFLUSH
        }

        barx(&g_cbc, &g_cbg, CREW);

        if (tid < KSEG) sinv[tid] = 1.f / (g_sumE[tid] + EPSF);
        __syncthreads();
        {
            int cur = seg_of(send, w0 + lane);
            float loc = 0.f;
            #pragma unroll 8
            for (int i = 0; i < 64; ++i) {
                int f = w0 + i * 32 + lane;
                if (f >= send[cur]) {
                    atomicAdd(&g_ent[cur], loc); loc = 0.f;
                    while (send[cur] <= f) cur++;
                }
                float p = energy[f] * sinv[cur];
                loc += p * __logf(p + EPSF);
            }
            atomicAdd(&g_ent[cur], loc);
        }

        barx(&g_cbc, &g_cbg, CREW);

        if (cb == 0 && tid < KSEG) {
            const int k = tid;
            const int s = segstart[k];
            const int e = segend[k];
            const float len = (float)(e - s);
            const float inv = 1.f / len;
            const int  iv  = fpsp[0];
            const float fps = (iv >= 1 && iv <= 1000000) ? (float)iv : __int_as_float(iv);
            float sk[8];
            sk[0] = log1pf(len / fps);
            sk[1] = log1pf((float)s / fps);
            sk[2] = log1pf(g_sumE[k] * inv);
            sk[3] = log1pf(__int_as_float(g_maxE[k]));
            sk[4] = log1pf(-g_ent[k]);
            sk[5] = log1pf(g_sumSC[k * 3 + 0] * inv);
            sk[6] = log1pf(g_sumSC[k * 3 + 1] * inv);
            sk[7] = log1pf(g_sumSC[k * 3 + 2] * inv);
            #pragma unroll
            for (int i = 0; i < 8; ++i) out[OUT_SK + k * 8 + i] = sk[i];
            float conf = g_sumFC[k] * inv;
            out[OUT_MASK + k] = (conf >= CONF_TH) ? 1.f : 0.f;
            out[OUT_TYPE + k] = (float)etype[k];
            out[OUT_CONF + k] = conf;
        }
    }
    #undef FLUSH4

    barx(&g_barc, &g_barg, G);

    // ================= GEMM =================
    {
        const int  iv  = fpsp[0];
        const float fps = (iv >= 1 && iv <= 1000000) ? (float)iv : __int_as_float(iv);

        for (int item = blockIdx.x; item < 256; item += G) {
            const int k  = item >> 2;
            const int s  = segstart[k];
            const int e  = segend[k];
            const float len = (float)(e - s);
            const float inv = 1.f / len;
            const int  ty   = etype[k];

            float sk[8];
            sk[0] = log1pf(len / fps);
            sk[1] = log1pf((float)s / fps);
            sk[2] = log1pf(g_sumE[k] * inv);
            sk[3] = log1pf(__int_as_float(g_maxE[k]));
            sk[4] = log1pf(-g_ent[k]);
            sk[5] = log1pf(g_sumSC[k * 3 + 0] * inv);
            sk[6] = log1pf(g_sumSC[k * 3 + 1] * inv);
            sk[7] = log1pf(g_sumSC[k * 3 + 2] * inv);

            for (int i = tid; i < ZDIM; i += NTH) {
                float v;
                if (i < DIN)            v = g_esum[k * DIN + i] * inv;
                else if (i < DIN + 8)   v = sk[i - DIN];
                else                    v = emb[ty * TYPEEMB + (i - DIN - 8)];
                z[i] = v;
            }
            __syncthreads();

            const int w     = tid >> 5;              // 16 warps
            const int lane  = tid & 31;
            const int mbase = (item & 3) * 64 + w * 4;
            #pragma unroll
            for (int r = 0; r < 4; ++r) {
                const int m = mbase + r;
                const float* Wr = W + (size_t)m * ZDIM;
                float acc = 0.f;
                for (int j = lane; j < ZDIM; j += 32) acc += z[j] * Wr[j];
                #pragma unroll
                for (int o = 16; o; o >>= 1) acc += __shfl_xor_sync(~0u, acc, o);
                if (lane == 0) out[OUT_TOKENS + k * DMODEL + m] = acc + bias[m];
            }
            __syncthreads();
        }
    }

    barx(&g_barc, &g_barg, G);

    // ================= re-zero scratch for next replay =================
    for (int i = blockIdx.x * NTH + tid; i < KSEG * DIN; i += G * NTH) g_esum[i] = 0.f;
    if (blockIdx.x == 0 && tid < KSEG) {
        g_sumE[tid] = 0.f; g_maxE[tid] = 0; g_sumFC[tid] = 0.f; g_ent[tid] = 0.f;
        g_sumSC[tid * 3 + 0] = 0.f; g_sumSC[tid * 3 + 1] = 0.f; g_sumSC[tid * 3 + 2] = 0.f;
    }
}

// ---------------------------------------------------------------------------
extern "C" void kernel_launch(void* const* d_in, const int* in_sizes, int n_in,
                              void* d_out, int out_size) {
    const float* features  = (const float*)d_in[0];
    const float* energy    = (const float*)d_in[1];
    const float* fconf     = (const float*)d_in[2];
    const float* sconf     = (const float*)d_in[3];
    const int*   seg_start = (const int*)  d_in[4];
    const int*   seg_end   = (const int*)  d_in[5];
    const int*   etype     = (const int*)  d_in[6];
    const float* emb       = (const float*)d_in[7];
    const float* W         = (const float*)d_in[8];
    const float* bias      = (const float*)d_in[9];
    const int*   fps       = (const int*)  d_in[10];
    float* out = (float*)d_out;

    cudaFuncSetAttribute(k_all, cudaFuncAttributeMaxDynamicSharedMemorySize, SMEM_DYN);

    int sms = 0, occ = 0;
    cudaDeviceGetAttribute(&sms, cudaDevAttrMultiProcessorCount, 0);
    cudaOccupancyMaxActiveBlocksPerMultiprocessor(&occ, k_all, NTH, SMEM_DYN);
    if (occ < 1) occ = 1;
    int grid = sms * occ;      // expect 2 CTAs/SM -> 304
    if (grid < CREW + 8) grid = CREW + 8;

    k_all<<<grid, NTH, SMEM_DYN>>>((const float4*)features, energy, fconf, sconf,
                                   seg_start, seg_end, etype, emb, W, bias, fps, out);
}

// round 16
// speedup vs baseline: 1.1892x; 1.1892x over previous
#include <cuda_runtime.h>
#include <cuda_bf16.h>
#include <cstdint>
#include <cstddef>

// ---------------------------------------------------------------------------
// EventTokenizer persistent kernel (1 block/SM, 1024 threads).  R14 base
// (best: 131.6us) + 4-way split bulk issue: each 32KB stage is fetched by
// FOUR 8KB cp.async.bulk ops (threads 0-3, own expect_tx each, mbar
// arrival count 4) -> 24 bulk ops in flight per SM instead of 6.
// Tests whether the ~14B/cyc/SM TMA delivery plateau is op-count-limited.
// ---------------------------------------------------------------------------

#define TFRAMES   262144
#define KSEG      64
#define DIN       512
#define DMODEL    256
#define TYPEEMB   32
#define ZDIM      552
#define EPSF      1e-6f
#define CONF_TH   0.3f

#define CH_FRAMES 16
#define CH_BYTES  (CH_FRAMES * DIN * 4)    // 32768
#define SUB_BYTES (CH_BYTES / 4)           // 8192
#define NCHUNK    (TFRAMES / CH_FRAMES)    // 16384
#define NSTAGE    6
#define SMEM_DYN  (NSTAGE * CH_BYTES)      // 196608
#define CREW      8
#define NTH       1024

// Output layout (float32, reference return order)
#define OUT_TOKENS 0
#define OUT_MASK   16384
#define OUT_TYPE   16448
#define OUT_CONF   16512
#define OUT_SK     16576

__device__ float    g_esum[KSEG * DIN];
__device__ float    g_sumE[KSEG];
__device__ int      g_maxE[KSEG];
__device__ float    g_sumFC[KSEG];
__device__ float    g_sumSC[KSEG * 3];
__device__ float    g_ent[KSEG];
__device__ unsigned g_barc = 0, g_barg = 0;    // grid barrier
__device__ unsigned g_cbc = 0, g_cbg = 0;      // crew barrier

__device__ __forceinline__ void barx(unsigned* cnt, unsigned* gen, unsigned n) {
    __syncthreads();
    if (threadIdx.x == 0) {
        __threadfence();
        unsigned g0 = *(volatile unsigned*)gen;
        if (atomicAdd(cnt, 1u) == n - 1u) {
            *cnt = 0;
            __threadfence();
            atomicAdd(gen, 1u);
        } else {
            while (*(volatile unsigned*)gen == g0) __nanosleep(128);
        }
        __threadfence();
    }
    __syncthreads();
}

__device__ __forceinline__ unsigned s2u(const void* p) {
    return (unsigned)__cvta_generic_to_shared(p);
}
__device__ __forceinline__ void mbar_init(unsigned a, unsigned cnt) {
    asm volatile("mbarrier.init.shared.b64 [%0], %1;" :: "r"(a), "r"(cnt) : "memory");
}
__device__ __forceinline__ void mbar_expect_tx(unsigned a, unsigned bytes) {
    asm volatile("mbarrier.arrive.expect_tx.shared.b64 _, [%0], %1;"
                 :: "r"(a), "r"(bytes) : "memory");
}
__device__ __forceinline__ void bulk_g2s(unsigned dst, const void* src,
                                         unsigned bytes, unsigned mbar) {
    asm volatile("cp.async.bulk.shared::cta.global.mbarrier::complete_tx::bytes "
                 "[%0], [%1], %2, [%3];"
                 :: "r"(dst), "l"(src), "r"(bytes), "r"(mbar) : "memory");
}
__device__ __forceinline__ void mbar_wait(unsigned a, unsigned parity) {
    unsigned done;
    do {
        asm volatile("{\n\t.reg .pred p;\n\t"
                     "mbarrier.try_wait.parity.shared.b64 p, [%1], %2;\n\t"
                     "selp.b32 %0, 1, 0, p;\n\t}"
                     : "=r"(done) : "r"(a), "r"(parity) : "memory");
    } while (!done);
}

__device__ __forceinline__ int seg_of(const int* send, int f) {
    int lo = 0, hi = KSEG - 1;
    #pragma unroll
    for (int it = 0; it < 6; ++it) {
        int mid = (lo + hi) >> 1;
        if (send[mid] > f) hi = mid; else lo = mid + 1;
    }
    return lo;
}

__global__ void __launch_bounds__(NTH)
k_all(const float4* __restrict__ feat,
      const float*  __restrict__ energy,
      const float*  __restrict__ fconf,
      const float*  __restrict__ sconf,
      const int*    __restrict__ segstart,
      const int*    __restrict__ segend,
      const int*    __restrict__ etype,
      const float*  __restrict__ emb,
      const float*  __restrict__ W,
      const float*  __restrict__ bias,
      const int*    __restrict__ fpsp,
      float*        __restrict__ out) {
    extern __shared__ __align__(16) char dsm[];
    __shared__ int   send[KSEG];
    __shared__ float sinv[KSEG];
    __shared__ float z[ZDIM];
    __shared__ alignas(8) unsigned long long mbar[NSTAGE];

    const int tid = threadIdx.x;
    const unsigned G = gridDim.x;
    const int GF = (int)G - CREW;
    if (tid < KSEG) send[tid] = segend[tid];
    if (tid == 0) {
        #pragma unroll
        for (int s = 0; s < NSTAGE; ++s) mbar_init(s2u(&mbar[s]), 4u);  // 4 issuers
    }
    __syncthreads();

    #define FLUSH4(curv, colv, a) do { \
        float* d_ = &g_esum[(curv) * DIN + (colv) * 4]; \
        atomicAdd(d_ + 0, (a).x); atomicAdd(d_ + 1, (a).y); \
        atomicAdd(d_ + 2, (a).z); atomicAdd(d_ + 3, (a).w); \
        (a).x = (a).y = (a).z = (a).w = 0.f; } while (0)

    // issue one stage as 4 sub-bulks; called by threads 0..3 (sub = tid)
    auto issue_sub = [&](int st, int chunk, int sub) {
        unsigned mb = s2u(&mbar[st]);
        mbar_expect_tx(mb, SUB_BYTES);
        bulk_g2s(s2u(dsm + st * CH_BYTES + sub * SUB_BYTES),
                 (const char*)feat + (size_t)chunk * CH_BYTES + (size_t)sub * SUB_BYTES,
                 SUB_BYTES, mb);
    };

    // TMA stream over contiguous chunks [c0,c1). 32 warps drain each stage:
    // thread handles frames [h*2, h*2+2), h = tid>>7 in 0..7, col = tid&127.
    auto tma_stream = [&](int c0, int c1) {
        const int n = c1 - c0;
        if (n <= 0) return;
        if (tid < 4) {
            const int pre = n < NSTAGE ? n : NSTAGE;
            for (int l = 0; l < pre; ++l) issue_sub(l, c0 + l, tid);
        }
        const int h   = tid >> 7;        // 0..7, frames [h*2, h*2+2)
        const int col = tid & 127;
        float4 acc = make_float4(0.f, 0.f, 0.f, 0.f);
        int cur = seg_of(send, c0 * CH_FRAMES + h * 2);
        int st = 0, ph = 0;
        for (int l = 0; l < n; ++l) {
            mbar_wait(s2u(&mbar[st]), (unsigned)ph);
            const int f0 = (c0 + l) * CH_FRAMES;
            const float4* sb = (const float4*)(dsm + st * CH_BYTES);
            const int first = f0 + h * 2;
            if (send[cur] <= first) { FLUSH4(cur, col, acc); cur = seg_of(send, first); }
            if (send[cur] >= first + 2) {
                float4 v0 = sb[(h * 2 + 0) * 128 + col];
                float4 v1 = sb[(h * 2 + 1) * 128 + col];
                acc.x += v0.x; acc.y += v0.y; acc.z += v0.z; acc.w += v0.w;
                acc.x += v1.x; acc.y += v1.y; acc.z += v1.z; acc.w += v1.w;
            } else {
                for (int f = first; f < first + 2; ++f) {
                    if (f >= send[cur]) { FLUSH4(cur, col, acc); cur = seg_of(send, f); }
                    float4 v = sb[(f - f0) * 128 + col];
                    acc.x += v.x; acc.y += v.y; acc.z += v.z; acc.w += v.w;
                }
            }
            __syncthreads();                    // stage fully drained
            if (tid < 4 && l + NSTAGE < n) issue_sub(st, c0 + l + NSTAGE, tid);
            if (++st == NSTAGE) { st = 0; ph ^= 1; }
        }
        FLUSH4(cur, col, acc);
    };

    if ((int)blockIdx.x < GF) {
        const int b  = blockIdx.x;
        const int c0 = (int)(((long long)b * NCHUNK) / GF);
        const int c1 = (int)(((long long)(b + 1) * NCHUNK) / GF);
        tma_stream(c0, c1);
    } else {
        // ============ crew: scalars -> entropy -> epilogue (hidden tail) ====
        const int cb   = blockIdx.x - GF;
        const int g    = cb * NTH + tid;          // 0..8191
        const int lane = g & 31;
        const int w0   = (g >> 5) * 1024;         // warp-contiguous 1024 frames

        {
            int cur = seg_of(send, w0 + lane);
            float sE = 0.f, mx = 0.f, aF = 0.f, s0 = 0.f, s1 = 0.f, s2 = 0.f;
            #define SFLUSH() do { \
                atomicAdd(&g_sumE[cur], sE); \
                atomicMax(&g_maxE[cur], __float_as_int(mx)); \
                atomicAdd(&g_sumFC[cur], aF); \
                atomicAdd(&g_sumSC[cur * 3 + 0], s0); \
                atomicAdd(&g_sumSC[cur * 3 + 1], s1); \
                atomicAdd(&g_sumSC[cur * 3 + 2], s2); \
                sE = mx = aF = s0 = s1 = s2 = 0.f; } while (0)
            #pragma unroll 8
            for (int i = 0; i < 32; ++i) {
                int f = w0 + i * 32 + lane;
                if (f >= send[cur]) { SFLUSH(); while (send[cur] <= f) cur++; }
                float e = energy[f];
                sE += e; mx = fmaxf(mx, e);
                aF += fconf[f];
                s0 += sconf[3 * f + 0]; s1 += sconf[3 * f + 1]; s2 += sconf[3 * f + 2];
            }
            SFLUSH();
            #undef SFLUSH
        }

        barx(&g_cbc, &g_cbg, CREW);

        if (tid < KSEG) sinv[tid] = 1.f / (g_sumE[tid] + EPSF);
        __syncthreads();
        {
            int cur = seg_of(send, w0 + lane);
            float loc = 0.f;
            #pragma unroll 8
            for (int i = 0; i < 32; ++i) {
                int f = w0 + i * 32 + lane;
                if (f >= send[cur]) {
                    atomicAdd(&g_ent[cur], loc); loc = 0.f;
                    while (send[cur] <= f) cur++;
                }
                float p = energy[f] * sinv[cur];
                loc += p * __logf(p + EPSF);
            }
            atomicAdd(&g_ent[cur], loc);
        }

        barx(&g_cbc, &g_cbg, CREW);

        if (cb == 0 && tid < KSEG) {
            const int k = tid;
            const int s = segstart[k];
            const int e = segend[k];
            const float len = (float)(e - s);
            const float inv = 1.f / len;
            const int  iv  = fpsp[0];
            const float fps = (iv >= 1 && iv <= 1000000) ? (float)iv : __int_as_float(iv);
            float sk[8];
            sk[0] = log1pf(len / fps);
            sk[1] = log1pf((float)s / fps);
            sk[2] = log1pf(g_sumE[k] * inv);
            sk[3] = log1pf(__int_as_float(g_maxE[k]));
            sk[4] = log1pf(-g_ent[k]);
            sk[5] = log1pf(g_sumSC[k * 3 + 0] * inv);
            sk[6] = log1pf(g_sumSC[k * 3 + 1] * inv);
            sk[7] = log1pf(g_sumSC[k * 3 + 2] * inv);
            #pragma unroll
            for (int i = 0; i < 8; ++i) out[OUT_SK + k * 8 + i] = sk[i];
            float conf = g_sumFC[k] * inv;
            out[OUT_MASK + k] = (conf >= CONF_TH) ? 1.f : 0.f;
            out[OUT_TYPE + k] = (float)etype[k];
            out[OUT_CONF + k] = conf;
        }
    }
    #undef FLUSH4

    barx(&g_barc, &g_barg, G);

    // ================= GEMM =================
    {
        const int  iv  = fpsp[0];
        const float fps = (iv >= 1 && iv <= 1000000) ? (float)iv : __int_as_float(iv);

        for (int item = blockIdx.x; item < 256; item += G) {
            const int k  = item >> 2;
            const int s  = segstart[k];
            const int e  = segend[k];
            const float len = (float)(e - s);
            const float inv = 1.f / len;
            const int  ty   = etype[k];

            float sk[8];
            sk[0] = log1pf(len / fps);
            sk[1] = log1pf((float)s / fps);
            sk[2] = log1pf(g_sumE[k] * inv);
            sk[3] = log1pf(__int_as_float(g_maxE[k]));
            sk[4] = log1pf(-g_ent[k]);
            sk[5] = log1pf(g_sumSC[k * 3 + 0] * inv);
            sk[6] = log1pf(g_sumSC[k * 3 + 1] * inv);
            sk[7] = log1pf(g_sumSC[k * 3 + 2] * inv);

            if (tid < ZDIM) {
                float v;
                if (tid < DIN)            v = g_esum[k * DIN + tid] * inv;
                else if (tid < DIN + 8)   v = sk[tid - DIN];
                else                      v = emb[ty * TYPEEMB + (tid - DIN - 8)];
                z[tid] = v;
            }
            __syncthreads();

            const int w     = tid >> 5;              // 32 warps
            const int lane  = tid & 31;
            const int mbase = (item & 3) * 64 + w * 2;
            #pragma unroll
            for (int r = 0; r < 2; ++r) {
                const int m = mbase + r;
                const float* Wr = W + (size_t)m * ZDIM;
                float acc = 0.f;
                for (int j = lane; j < ZDIM; j += 32) acc += z[j] * Wr[j];
                #pragma unroll
                for (int o = 16; o; o >>= 1) acc += __shfl_xor_sync(~0u, acc, o);
                if (lane == 0) out[OUT_TOKENS + k * DMODEL + m] = acc + bias[m];
            }
            __syncthreads();
        }
    }

    barx(&g_barc, &g_barg, G);

    // ================= re-zero scratch for next replay =================
    for (int i = blockIdx.x * NTH + tid; i < KSEG * DIN; i += G * NTH) g_esum[i] = 0.f;
    if (blockIdx.x == 0 && tid < KSEG) {
        g_sumE[tid] = 0.f; g_maxE[tid] = 0; g_sumFC[tid] = 0.f; g_ent[tid] = 0.f;
        g_sumSC[tid * 3 + 0] = 0.f; g_sumSC[tid * 3 + 1] = 0.f; g_sumSC[tid * 3 + 2] = 0.f;
    }
}

// ---------------------------------------------------------------------------
extern "C" void kernel_launch(void* const* d_in, const int* in_sizes, int n_in,
                              void* d_out, int out_size) {
    const float* features  = (const float*)d_in[0];
    const float* energy    = (const float*)d_in[1];
    const float* fconf     = (const float*)d_in[2];
    const float* sconf     = (const float*)d_in[3];
    const int*   seg_start = (const int*)  d_in[4];
    const int*   seg_end   = (const int*)  d_in[5];
    const int*   etype     = (const int*)  d_in[6];
    const float* emb       = (const float*)d_in[7];
    const float* W         = (const float*)d_in[8];
    const float* bias      = (const float*)d_in[9];
    const int*   fps       = (const int*)  d_in[10];
    float* out = (float*)d_out;

    cudaFuncSetAttribute(k_all, cudaFuncAttributeMaxDynamicSharedMemorySize, SMEM_DYN);

    int sms = 0, occ = 0;
    cudaDeviceGetAttribute(&sms, cudaDevAttrMultiProcessorCount, 0);
    cudaOccupancyMaxActiveBlocksPerMultiprocessor(&occ, k_all, NTH, SMEM_DYN);
    if (occ < 1) occ = 1;
    int grid = sms * occ;
    if (grid < CREW + 8) grid = CREW + 8;

    k_all<<<grid, NTH, SMEM_DYN>>>((const float4*)features, energy, fconf, sconf,
                                   seg_start, seg_end, etype, emb, W, bias, fps, out);
}

// round 17
// speedup vs baseline: 1.1968x; 1.0064x over previous
#include <cuda_runtime.h>
#include <cuda_bf16.h>
#include <cstdint>
#include <cstddef>

// ---------------------------------------------------------------------------
// EventTokenizer persistent kernel (1 block/SM, 1024 threads).  R16 base +
// 8-way split bulk issue: each 32KB stage is fetched by EIGHT 4KB
// cp.async.bulk ops (threads 0-7, own expect_tx each, mbar arrival count 8)
// -> 48 bulk ops in flight per SM. R16 proved op-count splitting raises
// TMA delivery (6->24 ops: 3.83->4.09 TB/s).
// ---------------------------------------------------------------------------

#define TFRAMES   262144
#define KSEG      64
#define DIN       512
#define DMODEL    256
#define TYPEEMB   32
#define ZDIM      552
#define EPSF      1e-6f
#define CONF_TH   0.3f

#define CH_FRAMES 16
#define CH_BYTES  (CH_FRAMES * DIN * 4)    // 32768
#define NSUB      8
#define SUB_BYTES (CH_BYTES / NSUB)        // 4096
#define NCHUNK    (TFRAMES / CH_FRAMES)    // 16384
#define NSTAGE    6
#define SMEM_DYN  (NSTAGE * CH_BYTES)      // 196608
#define CREW      8
#define NTH       1024

// Output layout (float32, reference return order)
#define OUT_TOKENS 0
#define OUT_MASK   16384
#define OUT_TYPE   16448
#define OUT_CONF   16512
#define OUT_SK     16576

__device__ float    g_esum[KSEG * DIN];
__device__ float    g_sumE[KSEG];
__device__ int      g_maxE[KSEG];
__device__ float    g_sumFC[KSEG];
__device__ float    g_sumSC[KSEG * 3];
__device__ float    g_ent[KSEG];
__device__ unsigned g_barc = 0, g_barg = 0;    // grid barrier
__device__ unsigned g_cbc = 0, g_cbg = 0;      // crew barrier

__device__ __forceinline__ void barx(unsigned* cnt, unsigned* gen, unsigned n) {
    __syncthreads();
    if (threadIdx.x == 0) {
        __threadfence();
        unsigned g0 = *(volatile unsigned*)gen;
        if (atomicAdd(cnt, 1u) == n - 1u) {
            *cnt = 0;
            __threadfence();
            atomicAdd(gen, 1u);
        } else {
            while (*(volatile unsigned*)gen == g0) __nanosleep(128);
        }
        __threadfence();
    }
    __syncthreads();
}

__device__ __forceinline__ unsigned s2u(const void* p) {
    return (unsigned)__cvta_generic_to_shared(p);
}
__device__ __forceinline__ void mbar_init(unsigned a, unsigned cnt) {
    asm volatile("mbarrier.init.shared.b64 [%0], %1;" :: "r"(a), "r"(cnt) : "memory");
}
__device__ __forceinline__ void mbar_expect_tx(unsigned a, unsigned bytes) {
    asm volatile("mbarrier.arrive.expect_tx.shared.b64 _, [%0], %1;"
                 :: "r"(a), "r"(bytes) : "memory");
}
__device__ __forceinline__ void bulk_g2s(unsigned dst, const void* src,
                                         unsigned bytes, unsigned mbar) {
    asm volatile("cp.async.bulk.shared::cta.global.mbarrier::complete_tx::bytes "
                 "[%0], [%1], %2, [%3];"
                 :: "r"(dst), "l"(src), "r"(bytes), "r"(mbar) : "memory");
}
__device__ __forceinline__ void mbar_wait(unsigned a, unsigned parity) {
    unsigned done;
    do {
        asm volatile("{\n\t.reg .pred p;\n\t"
                     "mbarrier.try_wait.parity.shared.b64 p, [%1], %2;\n\t"
                     "selp.b32 %0, 1, 0, p;\n\t}"
                     : "=r"(done) : "r"(a), "r"(parity) : "memory");
    } while (!done);
}

__device__ __forceinline__ int seg_of(const int* send, int f) {
    int lo = 0, hi = KSEG - 1;
    #pragma unroll
    for (int it = 0; it < 6; ++it) {
        int mid = (lo + hi) >> 1;
        if (send[mid] > f) hi = mid; else lo = mid + 1;
    }
    return lo;
}

__global__ void __launch_bounds__(NTH)
k_all(const float4* __restrict__ feat,
      const float*  __restrict__ energy,
      const float*  __restrict__ fconf,
      const float*  __restrict__ sconf,
      const int*    __restrict__ segstart,
      const int*    __restrict__ segend,
      const int*    __restrict__ etype,
      const float*  __restrict__ emb,
      const float*  __restrict__ W,
      const float*  __restrict__ bias,
      const int*    __restrict__ fpsp,
      float*        __restrict__ out) {
    extern __shared__ __align__(16) char dsm[];
    __shared__ int   send[KSEG];
    __shared__ float sinv[KSEG];
    __shared__ float z[ZDIM];
    __shared__ alignas(8) unsigned long long mbar[NSTAGE];

    const int tid = threadIdx.x;
    const unsigned G = gridDim.x;
    const int GF = (int)G - CREW;
    if (tid < KSEG) send[tid] = segend[tid];
    if (tid == 0) {
        #pragma unroll
        for (int s = 0; s < NSTAGE; ++s) mbar_init(s2u(&mbar[s]), (unsigned)NSUB);
    }
    __syncthreads();

    #define FLUSH4(curv, colv, a) do { \
        float* d_ = &g_esum[(curv) * DIN + (colv) * 4]; \
        atomicAdd(d_ + 0, (a).x); atomicAdd(d_ + 1, (a).y); \
        atomicAdd(d_ + 2, (a).z); atomicAdd(d_ + 3, (a).w); \
        (a).x = (a).y = (a).z = (a).w = 0.f; } while (0)

    // issue one stage as NSUB sub-bulks; called by threads 0..NSUB-1
    auto issue_sub = [&](int st, int chunk, int sub) {
        unsigned mb = s2u(&mbar[st]);
        mbar_expect_tx(mb, SUB_BYTES);
        bulk_g2s(s2u(dsm + st * CH_BYTES + sub * SUB_BYTES),
                 (const char*)feat + (size_t)chunk * CH_BYTES + (size_t)sub * SUB_BYTES,
                 SUB_BYTES, mb);
    };

    // TMA stream over contiguous chunks [c0,c1). 32 warps drain each stage:
    // thread handles frames [h*2, h*2+2), h = tid>>7 in 0..7, col = tid&127.
    auto tma_stream = [&](int c0, int c1) {
        const int n = c1 - c0;
        if (n <= 0) return;
        if (tid < NSUB) {
            const int pre = n < NSTAGE ? n : NSTAGE;
            for (int l = 0; l < pre; ++l) issue_sub(l, c0 + l, tid);
        }
        const int h   = tid >> 7;        // 0..7, frames [h*2, h*2+2)
        const int col = tid & 127;
        float4 acc = make_float4(0.f, 0.f, 0.f, 0.f);
        int cur = seg_of(send, c0 * CH_FRAMES + h * 2);
        int st = 0, ph = 0;
        for (int l = 0; l < n; ++l) {
            mbar_wait(s2u(&mbar[st]), (unsigned)ph);
            const int f0 = (c0 + l) * CH_FRAMES;
            const float4* sb = (const float4*)(dsm + st * CH_BYTES);
            const int first = f0 + h * 2;
            if (send[cur] <= first) { FLUSH4(cur, col, acc); cur = seg_of(send, first); }
            if (send[cur] >= first + 2) {
                float4 v0 = sb[(h * 2 + 0) * 128 + col];
                float4 v1 = sb[(h * 2 + 1) * 128 + col];
                acc.x += v0.x; acc.y += v0.y; acc.z += v0.z; acc.w += v0.w;
                acc.x += v1.x; acc.y += v1.y; acc.z += v1.z; acc.w += v1.w;
            } else {
                for (int f = first; f < first + 2; ++f) {
                    if (f >= send[cur]) { FLUSH4(cur, col, acc); cur = seg_of(send, f); }
                    float4 v = sb[(f - f0) * 128 + col];
                    acc.x += v.x; acc.y += v.y; acc.z += v.z; acc.w += v.w;
                }
            }
            __syncthreads();                    // stage fully drained
            if (tid < NSUB && l + NSTAGE < n) issue_sub(st, c0 + l + NSTAGE, tid);
            if (++st == NSTAGE) { st = 0; ph ^= 1; }
        }
        FLUSH4(cur, col, acc);
    };

    if ((int)blockIdx.x < GF) {
        const int b  = blockIdx.x;
        const int c0 = (int)(((long long)b * NCHUNK) / GF);
        const int c1 = (int)(((long long)(b + 1) * NCHUNK) / GF);
        tma_stream(c0, c1);
    } else {
        // ============ crew: scalars -> entropy -> epilogue (hidden tail) ====
        const int cb   = blockIdx.x - GF;
        const int g    = cb * NTH + tid;          // 0..8191
        const int lane = g & 31;
        const int w0   = (g >> 5) * 1024;         // warp-contiguous 1024 frames

        {
            int cur = seg_of(send, w0 + lane);
            float sE = 0.f, mx = 0.f, aF = 0.f, s0 = 0.f, s1 = 0.f, s2 = 0.f;
            #define SFLUSH() do { \
                atomicAdd(&g_sumE[cur], sE); \
                atomicMax(&g_maxE[cur], __float_as_int(mx)); \
                atomicAdd(&g_sumFC[cur], aF); \
                atomicAdd(&g_sumSC[cur * 3 + 0], s0); \
                atomicAdd(&g_sumSC[cur * 3 + 1], s1); \
                atomicAdd(&g_sumSC[cur * 3 + 2], s2); \
                sE = mx = aF = s0 = s1 = s2 = 0.f; } while (0)
            #pragma unroll 8
            for (int i = 0; i < 32; ++i) {
                int f = w0 + i * 32 + lane;
                if (f >= send[cur]) { SFLUSH(); while (send[cur] <= f) cur++; }
                float e = energy[f];
                sE += e; mx = fmaxf(mx, e);
                aF += fconf[f];
                s0 += sconf[3 * f + 0]; s1 += sconf[3 * f + 1]; s2 += sconf[3 * f + 2];
            }
            SFLUSH();
            #undef SFLUSH
        }

        barx(&g_cbc, &g_cbg, CREW);

        if (tid < KSEG) sinv[tid] = 1.f / (g_sumE[tid] + EPSF);
        __syncthreads();
        {
            int cur = seg_of(send, w0 + lane);
            float loc = 0.f;
            #pragma unroll 8
            for (int i = 0; i < 32; ++i) {
                int f = w0 + i * 32 + lane;
                if (f >= send[cur]) {
                    atomicAdd(&g_ent[cur], loc); loc = 0.f;
                    while (send[cur] <= f) cur++;
                }
                float p = energy[f] * sinv[cur];
                loc += p * __logf(p + EPSF);
            }
            atomicAdd(&g_ent[cur], loc);
        }

        barx(&g_cbc, &g_cbg, CREW);

        if (cb == 0 && tid < KSEG) {
            const int k = tid;
            const int s = segstart[k];
            const int e = segend[k];
            const float len = (float)(e - s);
            const float inv = 1.f / len;
            const int  iv  = fpsp[0];
            const float fps = (iv >= 1 && iv <= 1000000) ? (float)iv : __int_as_float(iv);
            float sk[8];
            sk[0] = log1pf(len / fps);
            sk[1] = log1pf((float)s / fps);
            sk[2] = log1pf(g_sumE[k] * inv);
            sk[3] = log1pf(__int_as_float(g_maxE[k]));
            sk[4] = log1pf(-g_ent[k]);
            sk[5] = log1pf(g_sumSC[k * 3 + 0] * inv);
            sk[6] = log1pf(g_sumSC[k * 3 + 1] * inv);
            sk[7] = log1pf(g_sumSC[k * 3 + 2] * inv);
            #pragma unroll
            for (int i = 0; i < 8; ++i) out[OUT_SK + k * 8 + i] = sk[i];
            float conf = g_sumFC[k] * inv;
            out[OUT_MASK + k] = (conf >= CONF_TH) ? 1.f : 0.f;
            out[OUT_TYPE + k] = (float)etype[k];
            out[OUT_CONF + k] = conf;
        }
    }
    #undef FLUSH4

    barx(&g_barc, &g_barg, G);

    // ================= GEMM =================
    {
        const int  iv  = fpsp[0];
        const float fps = (iv >= 1 && iv <= 1000000) ? (float)iv : __int_as_float(iv);

        for (int item = blockIdx.x; item < 256; item += G) {
            const int k  = item >> 2;
            const int s  = segstart[k];
            const int e  = segend[k];
            const float len = (float)(e - s);
            const float inv = 1.f / len;
            const int  ty   = etype[k];

            float sk[8];
            sk[0] = log1pf(len / fps);
            sk[1] = log1pf((float)s / fps);
            sk[2] = log1pf(g_sumE[k] * inv);
            sk[3] = log1pf(__int_as_float(g_maxE[k]));
            sk[4] = log1pf(-g_ent[k]);
            sk[5] = log1pf(g_sumSC[k * 3 + 0] * inv);
            sk[6] = log1pf(g_sumSC[k * 3 + 1] * inv);
            sk[7] = log1pf(g_sumSC[k * 3 + 2] * inv);

            if (tid < ZDIM) {
                float v;
                if (tid < DIN)            v = g_esum[k * DIN + tid] * inv;
                else if (tid < DIN + 8)   v = sk[tid - DIN];
                else                      v = emb[ty * TYPEEMB + (tid - DIN - 8)];
                z[tid] = v;
            }
            __syncthreads();

            const int w     = tid >> 5;              // 32 warps
            const int lane  = tid & 31;
            const int mbase = (item & 3) * 64 + w * 2;
            #pragma unroll
            for (int r = 0; r < 2; ++r) {
                const int m = mbase + r;
                const float* Wr = W + (size_t)m * ZDIM;
                float acc = 0.f;
                for (int j = lane; j < ZDIM; j += 32) acc += z[j] * Wr[j];
                #pragma unroll
                for (int o = 16; o; o >>= 1) acc += __shfl_xor_sync(~0u, acc, o);
                if (lane == 0) out[OUT_TOKENS + k * DMODEL + m] = acc + bias[m];
            }
            __syncthreads();
        }
    }

    barx(&g_barc, &g_barg, G);

    // ================= re-zero scratch for next replay =================
    for (int i = blockIdx.x * NTH + tid; i < KSEG * DIN; i += G * NTH) g_esum[i] = 0.f;
    if (blockIdx.x == 0 && tid < KSEG) {
        g_sumE[tid] = 0.f; g_maxE[tid] = 0; g_sumFC[tid] = 0.f; g_ent[tid] = 0.f;
        g_sumSC[tid * 3 + 0] = 0.f; g_sumSC[tid * 3 + 1] = 0.f; g_sumSC[tid * 3 + 2] = 0.f;
    }
}

// ---------------------------------------------------------------------------
extern "C" void kernel_launch(void* const* d_in, const int* in_sizes, int n_in,
                              void* d_out, int out_size) {
    const float* features  = (const float*)d_in[0];
    const float* energy    = (const float*)d_in[1];
    const float* fconf     = (const float*)d_in[2];
    const float* sconf     = (const float*)d_in[3];
    const int*   seg_start = (const int*)  d_in[4];
    const int*   seg_end   = (const int*)  d_in[5];
    const int*   etype     = (const int*)  d_in[6];
    const float* emb       = (const float*)d_in[7];
    const float* W         = (const float*)d_in[8];
    const float* bias      = (const float*)d_in[9];
    const int*   fps       = (const int*)  d_in[10];
    float* out = (float*)d_out;

    cudaFuncSetAttribute(k_all, cudaFuncAttributeMaxDynamicSharedMemorySize, SMEM_DYN);

    int sms = 0, occ = 0;
    cudaDeviceGetAttribute(&sms, cudaDevAttrMultiProcessorCount, 0);
    cudaOccupancyMaxActiveBlocksPerMultiprocessor(&occ, k_all, NTH, SMEM_DYN);
    if (occ < 1) occ = 1;
    int grid = sms * occ;
    if (grid < CREW + 8) grid = CREW + 8;

    k_all<<<grid, NTH, SMEM_DYN>>>((const float4*)features, energy, fconf, sconf,
                                   seg_start, seg_end, etype, emb, W, bias, fps, out);
}